// round 12
// baseline (speedup 1.0000x reference)
#include <cuda_runtime.h>

#define B_  2
#define H_  12
#define S_  2048
#define D_  64
#define BR  64
#define BC  64
#define NT  256
#define STRIDE 68
#define NITEMS ((S_ / BR) * H_ * B_)   // 768
#define NCTAS  296                     // 148 SMs x 2 CTAs

typedef unsigned long long ull;
typedef unsigned int u32;

__device__ int g_seg_start[B_ * S_];
__device__ u32 g_ctr;

__global__ void segstart_kernel(const int* __restrict__ block_ids) {
    int idx = blockIdx.x * blockDim.x + threadIdx.x;
    if (idx == 0) g_ctr = 0u;
    if (idx >= B_ * S_) return;
    int b = idx / S_, qpos = idx % S_;
    const int* bi = block_ids + b * S_;
    int val = bi[qpos];
    int lo = 0, hi = qpos;
    while (lo < hi) {
        int mid = (lo + hi) >> 1;
        if (bi[mid] < val) lo = mid + 1; else hi = mid;
    }
    g_seg_start[idx] = lo;
}

__device__ __forceinline__ ull fma2(ull a, ull b, ull c) {
    ull d;
    asm("fma.rn.f32x2 %0, %1, %2, %3;" : "=l"(d) : "l"(a), "l"(b), "l"(c));
    return d;
}
__device__ __forceinline__ ull pack2(float lo, float hi) {
    ull d;
    asm("mov.b64 %0, {%1, %2};" : "=l"(d) : "f"(lo), "f"(hi));
    return d;
}
__device__ __forceinline__ float2 unpack2(ull v) {
    float2 r;
    asm("mov.b64 {%0, %1}, %2;" : "=f"(r.x), "=f"(r.y) : "l"(v));
    return r;
}
__device__ __forceinline__ float ex2f(float x) {
    float y;
    asm("ex2.approx.ftz.f32 %0, %1;" : "=f"(y) : "f"(x));
    return y;
}
__device__ __forceinline__ u32 smem_u32(const void* p) {
    u32 a;
    asm("{ .reg .u64 t; cvta.to.shared.u64 t, %1; cvt.u32.u64 %0, t; }"
        : "=r"(a) : "l"(p));
    return a;
}
__device__ __forceinline__ void cp16(u32 dst, const void* src) {
    asm volatile("cp.async.cg.shared.global [%0], [%1], 16;"
                 :: "r"(dst), "l"(src) : "memory");
}
#define CP_COMMIT() asm volatile("cp.async.commit_group;" ::: "memory")
#define CP_WAIT0()  asm volatile("cp.async.wait_group 0;" ::: "memory")
#define PAIR_BAR(id) asm volatile("bar.sync %0, 64;" :: "r"(id) : "memory")

extern __shared__ float smem[];

__global__ __launch_bounds__(NT, 2)
void attn_kernel(const float* __restrict__ Q, const float* __restrict__ K,
                 const float* __restrict__ V, float* __restrict__ O) {
    float* Qs = smem;                       // [BR][STRIDE], pre-scaled
    float* Ps = Qs + BR * STRIDE;           // [BC][STRIDE] row-permuted P
    float* KV = Ps + BC * STRIDE;           // 2 x (K tile, V tile)
    const int TILE = BC * STRIDE;
    __shared__ float Lb[2 * BR];            // epilogue pair-partials
    __shared__ int s_item;

    const int t    = threadIdx.x;
    const int w    = t >> 5, lane = t & 31;
    const int prg  = w & 3;                 // pair group (ty-block); pair = {w, w^4}
    const int g    = w >> 2;                // tx-block
    const int ty   = prg * 4 + (lane >> 3); // rows ty+16i
    const int tx   = g * 8 + (lane & 7);    // QK cols tx+16j; PV dims [4tx,4tx+4)

    const int cr[4]  = { (t + 0*NT) >> 4, (t + 1*NT) >> 4, (t + 2*NT) >> 4, (t + 3*NT) >> 4 };
    const int cc4    = t & 15;
    const u32 kv_s   = smem_u32(KV);
    const float QSCALE = 0.125f * 1.44269504088896340736f;

    for (;;) {
        if (t == 0) s_item = (int)atomicAdd(&g_ctr, 1u);
        __syncthreads();          // broadcast item; fences prev item's smem use
        const int wk = s_item;
        if (wk >= NITEMS) return;

        // heavy-first heuristic: descending query-tile index
        const int qt = (S_ / BR - 1) - wk / (B_ * H_);
        const int hb = wk % (B_ * H_);
        const int h = hb % H_, b = hb / H_;

        const int q0 = qt * BR;
        const long base = ((long)(b * H_ + h)) * S_ * D_;
        const float* Qb = Q + base + (long)q0 * D_;
        const float* Kb = K + base;
        const float* Vb = V + base;

        const int kstart = (g_seg_start[b * S_ + q0] / BC) * BC;

        // prologue: prefetch first K/V tile into buffer 0
        {
            u32 kd = kv_s;
            u32 vd = kv_s + TILE * 4;
            #pragma unroll
            for (int u = 0; u < 4; u++) {
                u32 off = (u32)(cr[u] * STRIDE + cc4 * 4) * 4;
                cp16(kd + off, &Kb[(long)(kstart + cr[u]) * D_ + cc4 * 4]);
                cp16(vd + off, &Vb[(long)(kstart + cr[u]) * D_ + cc4 * 4]);
            }
            CP_COMMIT();
        }

        // load Q tile (pre-scaled: scores come out in log2 units)
        #pragma unroll
        for (int u = 0; u < 4; u++) {
            int idx = t + NT * u;
            int r = idx >> 4, c4 = idx & 15;
            float4 qv = *(const float4*)&Qb[r * D_ + c4 * 4];
            qv.x *= QSCALE; qv.y *= QSCALE; qv.z *= QSCALE; qv.w *= QSCALE;
            *(float4*)&Qs[r * STRIDE + c4 * 4] = qv;
        }

        int st[4];
        #pragma unroll
        for (int i = 0; i < 4; i++) st[i] = g_seg_start[b * S_ + q0 + ty + 16 * i];

        float l[4] = {0.f, 0.f, 0.f, 0.f};
        ull oacc[4][2];
        #pragma unroll
        for (int i = 0; i < 4; i++) { oacc[i][0] = 0ull; oacc[i][1] = 0ull; }

        int buf = 0;
        for (int kt = kstart; kt <= q0; kt += BC, buf ^= 1) {
            float* Ks = KV + buf * (2 * TILE);
            float* Vs = Ks + TILE;

            CP_WAIT0();
            __syncthreads();   // KV(kt) visible; all PV(kt-BC) readers done

            // QK: 4x4 fragment, f32x2 accumulation over d.
            // 4x8 warp rectangle: Q insts 64B/wf, K insts 128B = 1 wf each.
            ull acc[4][4];
            #pragma unroll
            for (int i = 0; i < 4; i++)
                #pragma unroll
                for (int j = 0; j < 4; j++) acc[i][j] = 0ull;

            #pragma unroll
            for (int d4 = 0; d4 < 16; d4++) {
                ulonglong2 qp[4];
                #pragma unroll
                for (int i = 0; i < 4; i++)
                    qp[i] = *(ulonglong2*)&Qs[(ty + 16 * i) * STRIDE + d4 * 4];
                #pragma unroll
                for (int j = 0; j < 4; j++) {
                    ulonglong2 kp = *(ulonglong2*)&Ks[(tx + 16 * j) * STRIDE + d4 * 4];
                    #pragma unroll
                    for (int i = 0; i < 4; i++) {
                        acc[i][j] = fma2(qp[i].x, kp.x, acc[i][j]);
                        acc[i][j] = fma2(qp[i].y, kp.y, acc[i][j]);
                    }
                }
            }

            // prefetch next tile into buf^1 EARLY: overlaps exp2 + P store + PV
            if (kt + BC <= q0) {
                u32 kd = kv_s + (u32)((buf ^ 1) * (2 * TILE) * 4);
                u32 vd = kd + TILE * 4;
                #pragma unroll
                for (int u = 0; u < 4; u++) {
                    u32 off = (u32)(cr[u] * STRIDE + cc4 * 4) * 4;
                    cp16(kd + off, &Kb[(long)(kt + BC + cr[u]) * D_ + cc4 * 4]);
                    cp16(vd + off, &Vb[(long)(kt + BC + cr[u]) * D_ + cc4 * 4]);
                }
                CP_COMMIT();
            }

            // mask + exp2, partial l (unstable ghost-softmax, validated r5)
            float pr[4][4];
            #pragma unroll
            for (int i = 0; i < 4; i++) {
                int rg = q0 + ty + 16 * i;
                #pragma unroll
                for (int j = 0; j < 4; j++) {
                    float2 f = unpack2(acc[i][j]);
                    float s = f.x + f.y;
                    int cg = kt + tx + 16 * j;
                    bool in = (cg >= st[i]) & (cg <= rg);
                    pr[i][j] = in ? ex2f(s) : 0.f;
                }
                l[i] += (pr[i][0] + pr[i][1]) + (pr[i][2] + pr[i][3]);
            }

            // store P row-permuted: row (ty+16i) -> slot ty*4+i.
            // P slots [16*prg, 16*prg+16) are OWNED by pair {w, w^4}: the
            // exchange is pair-local -> 2-warp named barrier, not CTA barrier.
            #pragma unroll
            for (int j = 0; j < 4; j++) {
                float4 wv = make_float4(pr[0][j], pr[1][j], pr[2][j], pr[3][j]);
                *(float4*)&Ps[(tx + 16 * j) * STRIDE + ty * 4] = wv;
            }
            PAIR_BAR(1 + prg);   // P visible within pair

            // PV: per key, 2 LDS (both 1 wavefront now) + 4 MOV + 8 FFMA2
            #pragma unroll 16
            for (int k = 0; k < BC; k++) {
                float4 pf = *(float4*)&Ps[k * STRIDE + ty * 4];
                ulonglong2 vf = *(ulonglong2*)&Vs[k * STRIDE + tx * 4];
                ull pb0 = pack2(pf.x, pf.x);
                ull pb1 = pack2(pf.y, pf.y);
                ull pb2 = pack2(pf.z, pf.z);
                ull pb3 = pack2(pf.w, pf.w);
                oacc[0][0] = fma2(pb0, vf.x, oacc[0][0]);
                oacc[0][1] = fma2(pb0, vf.y, oacc[0][1]);
                oacc[1][0] = fma2(pb1, vf.x, oacc[1][0]);
                oacc[1][1] = fma2(pb1, vf.y, oacc[1][1]);
                oacc[2][0] = fma2(pb2, vf.x, oacc[2][0]);
                oacc[2][1] = fma2(pb2, vf.y, oacc[2][1]);
                oacc[3][0] = fma2(pb3, vf.x, oacc[3][0]);
                oacc[3][1] = fma2(pb3, vf.y, oacc[3][1]);
            }
        }

        // epilogue: reduce l over 8-lane group, exchange pair halves via Lb
        float ls4[4];
        #pragma unroll
        for (int i = 0; i < 4; i++) {
            float ls = l[i];
            #pragma unroll
            for (int off = 1; off < 8; off <<= 1)
                ls += __shfl_xor_sync(0xffffffffu, ls, off);
            ls4[i] = ls;
            if ((lane & 7) == 0) Lb[g * BR + ty + 16 * i] = ls;
        }
        PAIR_BAR(1 + prg);
        #pragma unroll
        for (int i = 0; i < 4; i++) {
            float tot = 1.f + ls4[i] + Lb[(g ^ 1) * BR + ty + 16 * i];
            float inv = 1.f / tot;
            int row = q0 + ty + 16 * i;
            float* op = (float*)O + base + (long)row * D_ + 4 * tx;
            float2 o0 = unpack2(oacc[i][0]);
            float2 o1 = unpack2(oacc[i][1]);
            *(float4*)op = make_float4(o0.x * inv, o0.y * inv, o1.x * inv, o1.y * inv);
        }
    }
}

extern "C" void kernel_launch(void* const* d_in, const int* in_sizes, int n_in,
                              void* d_out, int out_size) {
    const float* q  = (const float*)d_in[0];
    const float* k  = (const float*)d_in[1];
    const float* v  = (const float*)d_in[2];
    const int* bids = (const int*)d_in[3];
    float* out      = (float*)d_out;

    segstart_kernel<<<(B_ * S_ + 255) / 256, 256>>>(bids);

    const int smem_bytes = 6 * BC * STRIDE * (int)sizeof(float);  // 104448
    cudaFuncSetAttribute(attn_kernel, cudaFuncAttributeMaxDynamicSharedMemorySize,
                         smem_bytes);
    attn_kernel<<<NCTAS, NT, smem_bytes>>>(q, k, v, out);
}

// round 13
// speedup vs baseline: 1.7439x; 1.7439x over previous
#include <cuda_runtime.h>

#define B_  2
#define H_  12
#define S_  2048
#define D_  64
#define BR  128
#define BC  64
#define NT  256
#define KST 72                          // bf16 row stride (144B, LDSM conflict-free)
#define NITEMS ((S_ / BR) * H_ * B_)    // 384
#define NCTAS  296

typedef unsigned int u32;

__device__ int g_seg_start[B_ * S_];
__device__ u32 g_ctr;

__global__ void segstart_kernel(const int* __restrict__ block_ids) {
    int idx = blockIdx.x * blockDim.x + threadIdx.x;
    if (idx == 0) g_ctr = 0u;
    if (idx >= B_ * S_) return;
    int b = idx / S_, qpos = idx % S_;
    const int* bi = block_ids + b * S_;
    int val = bi[qpos];
    int lo = 0, hi = qpos;
    while (lo < hi) {
        int mid = (lo + hi) >> 1;
        if (bi[mid] < val) lo = mid + 1; else hi = mid;
    }
    g_seg_start[idx] = lo;
}

__device__ __forceinline__ u32 smem_u32(const void* p) {
    u32 a;
    asm("{ .reg .u64 t; cvta.to.shared.u64 t, %1; cvt.u32.u64 %0, t; }"
        : "=r"(a) : "l"(p));
    return a;
}
__device__ __forceinline__ float ex2f(float x) {
    float y; asm("ex2.approx.ftz.f32 %0, %1;" : "=f"(y) : "f"(x)); return y;
}
// split pair (e=even/lower, o=odd/upper) into bf16x2 hi word + residual lo word
__device__ __forceinline__ void bsplit(float e, float o, u32& hi, u32& lo) {
    asm("cvt.rn.bf16x2.f32 %0, %1, %2;" : "=r"(hi) : "f"(o), "f"(e));
    float eh = __uint_as_float(hi << 16);
    float oh = __uint_as_float(hi & 0xFFFF0000u);
    asm("cvt.rn.bf16x2.f32 %0, %1, %2;" : "=r"(lo) : "f"(o - oh), "f"(e - eh));
}
__device__ __forceinline__ void ldsm4(u32* r, u32 a) {
    asm volatile("ldmatrix.sync.aligned.m8n8.x4.shared.b16 {%0,%1,%2,%3}, [%4];"
                 : "=r"(r[0]), "=r"(r[1]), "=r"(r[2]), "=r"(r[3]) : "r"(a));
}
__device__ __forceinline__ void ldsm4t(u32* r, u32 a) {
    asm volatile("ldmatrix.sync.aligned.m8n8.x4.trans.shared.b16 {%0,%1,%2,%3}, [%4];"
                 : "=r"(r[0]), "=r"(r[1]), "=r"(r[2]), "=r"(r[3]) : "r"(a));
}
__device__ __forceinline__ void mma16816(float* d, const u32* a, u32 b0, u32 b1) {
    asm volatile(
        "mma.sync.aligned.m16n8k16.row.col.f32.bf16.bf16.f32 "
        "{%0,%1,%2,%3},{%4,%5,%6,%7},{%8,%9},{%0,%1,%2,%3};"
        : "+f"(d[0]), "+f"(d[1]), "+f"(d[2]), "+f"(d[3])
        : "r"(a[0]), "r"(a[1]), "r"(a[2]), "r"(a[3]), "r"(b0), "r"(b1));
}

extern __shared__ char dsm[];

__global__ __launch_bounds__(NT, 2)
void attn_kernel(const float* __restrict__ Q, const float* __restrict__ K,
                 const float* __restrict__ V, float* __restrict__ O) {
    __shared__ int s_item;
    const u32 base = smem_u32(dsm);
    const u32 QH = base, QL = base + 18432;
    const u32 KH = base + 36864, KL = base + 46080;
    const u32 VH = base + 55296, VL = base + 64512;

    const int t = threadIdx.x;
    const int w = t >> 5, lane = t & 31;
    const int g = lane >> 2, qd = lane & 3;

    // conversion slices
    const int ckey = t >> 2, cdg = (t & 3) * 16;      // K/V: 1 key x 16 dims
    const int qr = t >> 1, qhh = (t & 1) * 32;        // Q: 1 row x 32 dims

    // ldmatrix per-lane byte offsets
    const u32 a_off = (u32)(((lane & 15) * KST + 8 * (lane >> 4)) * 2);
    const u32 bk_off = (u32)((((lane & 7) + ((lane >= 16) ? 8 : 0)) * KST
                              + 8 * ((lane >> 3) & 1)) * 2);
    const u32 v_off = (u32)((((lane & 7) + 8 * ((lane >> 3) & 1)) * KST
                             + ((lane >= 16) ? 8 : 0)) * 2);
    const u32 arow_off = (u32)(16 * w * KST * 2);

    const float QSCALE = 0.125f * 1.44269504088896340736f;

    for (;;) {
        if (t == 0) s_item = (int)atomicAdd(&g_ctr, 1u);
        __syncthreads();
        const int wk = s_item;
        if (wk >= NITEMS) return;

        const int qt = (S_ / BR - 1) - wk / (B_ * H_);   // heavy-first
        const int hb = wk % (B_ * H_);
        const int h = hb % H_, b = hb / H_;
        const int q0 = qt * BR;
        const long gbase = ((long)(b * H_ + h)) * S_ * D_;
        const float* Qb = Q + gbase + (long)q0 * D_;
        const float* Kb = K + gbase;
        const float* Vb = V + gbase;

        // ---- Q convert (once per item): prescale, split, store bf16 hi/lo ----
        {
            const float4* src = (const float4*)&Qb[qr * D_ + qhh];
            u32 hh[16], ll[16];
            #pragma unroll
            for (int i = 0; i < 8; i++) {
                float4 f = src[i];
                f.x *= QSCALE; f.y *= QSCALE; f.z *= QSCALE; f.w *= QSCALE;
                bsplit(f.x, f.y, hh[2 * i], ll[2 * i]);
                bsplit(f.z, f.w, hh[2 * i + 1], ll[2 * i + 1]);
            }
            u32 off = (u32)((qr * KST + qhh) * 2);
            #pragma unroll
            for (int i = 0; i < 4; i++) {
                asm volatile("st.shared.v4.b32 [%0], {%1,%2,%3,%4};" ::
                    "r"(QH + off + 16 * i), "r"(hh[4*i]), "r"(hh[4*i+1]),
                    "r"(hh[4*i+2]), "r"(hh[4*i+3]));
                asm volatile("st.shared.v4.b32 [%0], {%1,%2,%3,%4};" ::
                    "r"(QL + off + 16 * i), "r"(ll[4*i]), "r"(ll[4*i+1]),
                    "r"(ll[4*i+2]), "r"(ll[4*i+3]));
            }
        }

        const int rg0 = q0 + 16 * w + g, rg1 = rg0 + 8;
        const int st0 = g_seg_start[b * S_ + rg0];
        const int st1 = g_seg_start[b * S_ + rg1];
        const int kstart = (g_seg_start[b * S_ + q0] / BC) * BC;

        float Oa[32];
        #pragma unroll
        for (int i = 0; i < 32; i++) Oa[i] = 0.f;
        float l0 = 0.f, l1 = 0.f;

        for (int kt = kstart; kt <= q0 + 64; kt += BC) {
            __syncthreads();   // prev tile's ldmatrix readers done; Q stores visible

            // ---- K/V convert: fp32 -> bf16 hi/lo, [key][dim], stride KST ----
            {
                const float4* ks4 = (const float4*)&Kb[(long)(kt + ckey) * D_ + cdg];
                const float4* vs4 = (const float4*)&Vb[(long)(kt + ckey) * D_ + cdg];
                u32 off = (u32)((ckey * KST + cdg) * 2);
                u32 h8[8], l8[8];
                #pragma unroll
                for (int i = 0; i < 4; i++) {
                    float4 f = ks4[i];
                    bsplit(f.x, f.y, h8[2*i], l8[2*i]);
                    bsplit(f.z, f.w, h8[2*i+1], l8[2*i+1]);
                }
                asm volatile("st.shared.v4.b32 [%0], {%1,%2,%3,%4};" ::
                    "r"(KH + off), "r"(h8[0]), "r"(h8[1]), "r"(h8[2]), "r"(h8[3]));
                asm volatile("st.shared.v4.b32 [%0], {%1,%2,%3,%4};" ::
                    "r"(KH + off + 16), "r"(h8[4]), "r"(h8[5]), "r"(h8[6]), "r"(h8[7]));
                asm volatile("st.shared.v4.b32 [%0], {%1,%2,%3,%4};" ::
                    "r"(KL + off), "r"(l8[0]), "r"(l8[1]), "r"(l8[2]), "r"(l8[3]));
                asm volatile("st.shared.v4.b32 [%0], {%1,%2,%3,%4};" ::
                    "r"(KL + off + 16), "r"(l8[4]), "r"(l8[5]), "r"(l8[6]), "r"(l8[7]));
                #pragma unroll
                for (int i = 0; i < 4; i++) {
                    float4 f = vs4[i];
                    bsplit(f.x, f.y, h8[2*i], l8[2*i]);
                    bsplit(f.z, f.w, h8[2*i+1], l8[2*i+1]);
                }
                asm volatile("st.shared.v4.b32 [%0], {%1,%2,%3,%4};" ::
                    "r"(VH + off), "r"(h8[0]), "r"(h8[1]), "r"(h8[2]), "r"(h8[3]));
                asm volatile("st.shared.v4.b32 [%0], {%1,%2,%3,%4};" ::
                    "r"(VH + off + 16), "r"(h8[4]), "r"(h8[5]), "r"(h8[6]), "r"(h8[7]));
                asm volatile("st.shared.v4.b32 [%0], {%1,%2,%3,%4};" ::
                    "r"(VL + off), "r"(l8[0]), "r"(l8[1]), "r"(l8[2]), "r"(l8[3]));
                asm volatile("st.shared.v4.b32 [%0], {%1,%2,%3,%4};" ::
                    "r"(VL + off + 16), "r"(l8[4]), "r"(l8[5]), "r"(l8[6]), "r"(l8[7]));
            }
            __syncthreads();

            // ---- QK: S = Qh*Kh + Qh*Kl + Ql*Kh (fp32 accum) ----
            float Sa[32];
            #pragma unroll
            for (int i = 0; i < 32; i++) Sa[i] = 0.f;
            u32 ah[16];
            #pragma unroll
            for (int ks = 0; ks < 4; ks++)
                ldsm4(&ah[4 * ks], QH + arow_off + a_off + 32 * ks);
            #pragma unroll
            for (int ks = 0; ks < 4; ks++) {
                #pragma unroll
                for (int jp = 0; jp < 4; jp++) {
                    u32 bh[4], bl[4];
                    ldsm4(bh, KH + bk_off + (u32)(jp * 2304 + ks * 32));
                    ldsm4(bl, KL + bk_off + (u32)(jp * 2304 + ks * 32));
                    mma16816(&Sa[8 * jp],     &ah[4 * ks], bh[0], bh[1]);
                    mma16816(&Sa[8 * jp + 4], &ah[4 * ks], bh[2], bh[3]);
                    mma16816(&Sa[8 * jp],     &ah[4 * ks], bl[0], bl[1]);
                    mma16816(&Sa[8 * jp + 4], &ah[4 * ks], bl[2], bl[3]);
                }
            }
            #pragma unroll
            for (int ks = 0; ks < 4; ks++)
                ldsm4(&ah[4 * ks], QL + arow_off + a_off + 32 * ks);
            #pragma unroll
            for (int ks = 0; ks < 4; ks++) {
                #pragma unroll
                for (int jp = 0; jp < 4; jp++) {
                    u32 bh[4];
                    ldsm4(bh, KH + bk_off + (u32)(jp * 2304 + ks * 32));
                    mma16816(&Sa[8 * jp],     &ah[4 * ks], bh[0], bh[1]);
                    mma16816(&Sa[8 * jp + 4], &ah[4 * ks], bh[2], bh[3]);
                }
            }

            // ---- mask + exp2 (ghost-softmax, unstable form) -> P A-frags ----
            u32 ph[16], pl[16];
            float la0 = 0.f, la1 = 0.f;
            #pragma unroll
            for (int j = 0; j < 8; j++) {
                const float* s4 = &Sa[4 * j];
                int c0 = kt + 8 * j + 2 * qd, c1 = c0 + 1;
                float p0 = (c0 >= st0 && c0 <= rg0) ? ex2f(s4[0]) : 0.f;
                float p1 = (c1 >= st0 && c1 <= rg0) ? ex2f(s4[1]) : 0.f;
                float p2 = (c0 >= st1 && c0 <= rg1) ? ex2f(s4[2]) : 0.f;
                float p3 = (c1 >= st1 && c1 <= rg1) ? ex2f(s4[3]) : 0.f;
                la0 += p0 + p1; la1 += p2 + p3;
                int idx = 4 * (j >> 1) + 2 * (j & 1);
                bsplit(p0, p1, ph[idx],     pl[idx]);
                bsplit(p2, p3, ph[idx + 1], pl[idx + 1]);
            }
            l0 += la0; l1 += la1;

            // ---- PV: O += Ph*Vh + Ph*Vl + Pl*Vh (P from registers, FA2-style) ----
            #pragma unroll
            for (int ks = 0; ks < 4; ks++) {
                #pragma unroll
                for (int jp = 0; jp < 4; jp++) {
                    u32 bh[4], bl[4];
                    ldsm4t(bh, VH + v_off + (u32)(ks * 2304 + jp * 32));
                    ldsm4t(bl, VL + v_off + (u32)(ks * 2304 + jp * 32));
                    mma16816(&Oa[8 * jp],     &ph[4 * ks], bh[0], bh[1]);
                    mma16816(&Oa[8 * jp + 4], &ph[4 * ks], bh[2], bh[3]);
                    mma16816(&Oa[8 * jp],     &ph[4 * ks], bl[0], bl[1]);
                    mma16816(&Oa[8 * jp + 4], &ph[4 * ks], bl[2], bl[3]);
                    mma16816(&Oa[8 * jp],     &pl[4 * ks], bh[0], bh[1]);
                    mma16816(&Oa[8 * jp + 4], &pl[4 * ks], bh[2], bh[3]);
                }
            }
        }

        // ---- epilogue: l reduce within quad, normalize (ghost +1), store ----
        l0 += __shfl_xor_sync(0xffffffffu, l0, 1);
        l0 += __shfl_xor_sync(0xffffffffu, l0, 2);
        l1 += __shfl_xor_sync(0xffffffffu, l1, 1);
        l1 += __shfl_xor_sync(0xffffffffu, l1, 2);
        float inv0 = 1.f / (1.f + l0), inv1 = 1.f / (1.f + l1);
        float* Ob = (float*)O + gbase;
        #pragma unroll
        for (int j = 0; j < 8; j++) {
            int dc = 8 * j + 2 * qd;
            *(float2*)&Ob[(long)rg0 * D_ + dc] =
                make_float2(Oa[4 * j] * inv0, Oa[4 * j + 1] * inv0);
            *(float2*)&Ob[(long)rg1 * D_ + dc] =
                make_float2(Oa[4 * j + 2] * inv1, Oa[4 * j + 3] * inv1);
        }
    }
}

extern "C" void kernel_launch(void* const* d_in, const int* in_sizes, int n_in,
                              void* d_out, int out_size) {
    const float* q  = (const float*)d_in[0];
    const float* k  = (const float*)d_in[1];
    const float* v  = (const float*)d_in[2];
    const int* bids = (const int*)d_in[3];
    float* out      = (float*)d_out;

    segstart_kernel<<<(B_ * S_ + 255) / 256, 256>>>(bids);

    // QH/QL 2x18432 + KH/KL 2x9216 + VH/VL 2x9216 = 73728 bytes (2 CTAs/SM)
    const int smem_bytes = 73728;
    cudaFuncSetAttribute(attn_kernel, cudaFuncAttributeMaxDynamicSharedMemorySize,
                         smem_bytes);
    attn_kernel<<<NCTAS, NT, smem_bytes>>>(q, k, v, out);
}